// round 10
// baseline (speedup 1.0000x reference)
#include <cuda_runtime.h>
#include <cuda_fp16.h>
#include <cstdint>

// Problem constants
#define BB 256
#define NN 400
#define HH 512
#define EE 256
#define VV 50000
#define OOV 50
#define TT 49
#define D2H 1024   // 2*H
#define H4 2048    // 4*H

// ---------------- scratch (static device globals; no runtime alloc) -------
__device__ float g_cat1280[BB * 1280];
__device__ float g_x[BB * EE];
__device__ float g_cat768[BB * 768];
__device__ float g_w768[H4 * 768];
__device__ float g_gates[BB * H4];
__device__ float g_sthat[BB * D2H];
__device__ float g_sdec[BB * D2H];
__device__ float g_hdec[BB * HH];
__device__ float g_et[BB * NN];
__device__ float g_at[BB * NN];
__device__ float g_etd[BB * TT];
__device__ float g_atd[BB * TT];
__device__ float g_ctd[BB * HH];
__device__ float g_cat2816[BB * 2816];
__device__ float g_pgen[BB];
__device__ float g_cat2048[BB * H4];
__device__ float g_out2[BB * HH];
__device__ float g_logits[(size_t)BB * VV];
__device__ float g_etpart[8 * BB * NN];
__device__ __half g_ench[(size_t)BB * NN * D2H];   // enc_out in fp16 (210MB)
__device__ __half g_wh16[D2H * D2H];               // Wh in fp16

__device__ __forceinline__ float tanh_mufu(float x) {
    float y;
    asm("tanh.approx.f32 %0, %1;" : "=f"(y) : "f"(x));
    return y;
}

__device__ __forceinline__ unsigned pack_h2(float a, float b) {
    __half2 h = __floats2half2_rn(a, b);
    return *reinterpret_cast<unsigned*>(&h);
}

__device__ __forceinline__ uint32_t smem_u32(const void* p) {
    uint32_t a;
    asm("{ .reg .u64 t; cvta.to.shared.u64 t, %1; cvt.u32.u64 %0, t; }" : "=r"(a) : "l"(p));
    return a;
}

#define CP_ASYNC16(dst, src) \
    asm volatile("cp.async.cg.shared.global [%0], [%1], 16;" :: "r"(dst), "l"(src) : "memory")
#define CP_COMMIT() asm volatile("cp.async.commit_group;" ::: "memory")
#define CP_WAIT2()  asm volatile("cp.async.wait_group 2;" ::: "memory")

#define LDSM_X4(r0, r1, r2, r3, addr) \
    asm volatile("ldmatrix.sync.aligned.m8n8.x4.shared.b16 {%0,%1,%2,%3}, [%4];" \
        : "=r"(r0), "=r"(r1), "=r"(r2), "=r"(r3) : "r"(addr))

// fp16-accumulate MMA: C(f16x2 x2) += A x B
__device__ __forceinline__ void mma_f16acc(unsigned* c, const unsigned* a, const unsigned* b) {
    asm volatile(
        "mma.sync.aligned.m16n8k16.row.col.f16.f16.f16.f16 "
        "{%0,%1}, {%2,%3,%4,%5}, {%6,%7}, {%0,%1};\n"
        : "+r"(c[0]), "+r"(c[1])
        : "r"(a[0]), "r"(a[1]), "r"(a[2]), "r"(a[3]), "r"(b[0]), "r"(b[1]));
}

// ---------------- fp32->fp16 pre-convert (enc_out + Wh) -------------------
#define ENC4 (BB * NN * D2H / 4)
#define WH4  (D2H * D2H / 4)
__global__ void k_cvt(const float* __restrict__ enc, const float* __restrict__ wh) {
    int i = blockIdx.x * 256 + threadIdx.x;
    if (i >= ENC4 + WH4) return;
    float4 v;
    __half2* dst;
    if (i < ENC4) {
        v = reinterpret_cast<const float4*>(enc)[i];
        dst = reinterpret_cast<__half2*>(g_ench + (size_t)i * 4);
    } else {
        v = reinterpret_cast<const float4*>(wh)[i - ENC4];
        dst = reinterpret_cast<__half2*>(g_wh16 + (size_t)(i - ENC4) * 4);
    }
    dst[0] = __floats2half2_rn(v.x, v.y);
    dst[1] = __floats2half2_rn(v.z, v.w);
}

// ============================================================================
// Big attention-score kernel: fp16 inputs, cp.async 4-stage pipeline,
// ldmatrix.x4 fragment loads, f16 MMA accumulation (K=64 split -> f32).
// Block tile 128(M) x 128(N) x 32(K), 32 k-iters. grid (8, 800), x = d-tile.
// ============================================================================
#define STG_BYTES 20480
__global__ void __launch_bounds__(256, 1)
attn16(const __half* __restrict__ A, const __half* __restrict__ W,
       const float* __restrict__ bias, const float* __restrict__ v,
       float* __restrict__ et_part) {
    extern __shared__ __align__(16) char smem[];
    uint32_t sb = smem_u32(smem);

    int tid = threadIdx.x;
    int wid = tid >> 5, lane = tid & 31;
    int g = lane >> 2, tig = lane & 3;
    int wm = wid & 3, wn = wid >> 2;
    int d0 = blockIdx.x * 128, m0 = blockIdx.y * 128;

    // cp.async source/dest
    int r0 = tid >> 2, c0 = tid & 3;
    int r1 = (tid + 256) >> 2;
    const __half* Asrc0 = A + (size_t)(m0 + r0) * D2H + c0 * 8;
    const __half* Asrc1 = A + (size_t)(m0 + r1) * D2H + c0 * 8;
    const __half* Wsrc0 = W + (size_t)(d0 + r0) * D2H + c0 * 8;
    const __half* Wsrc1 = W + (size_t)(d0 + r1) * D2H + c0 * 8;
    uint32_t dA0 = r0 * 80 + c0 * 16, dA1 = r1 * 80 + c0 * 16;

    // ldmatrix per-lane offsets:
    // A x4 covers [m0-7,k0-7],[m8-15,k0-7],[m0-7,k8-15],[m8-15,k8-15]
    uint32_t a_off = (uint32_t)((wm * 32 + ((lane >> 3) & 1) * 8 + (lane & 7)) * 80
                                + (lane >> 4) * 16);
    // B x4 covers [n0-7,k0-7],[n0-7,k8-15],[n8-15,k0-7],[n8-15,k8-15]
    uint32_t b_off = (uint32_t)(10240 + (wn * 64 + (lane >> 4) * 8 + (lane & 7)) * 80
                                + ((lane >> 3) & 1) * 16);

    // prologue: fill stages 0..2
#pragma unroll
    for (int s = 0; s < 3; s++) {
        uint32_t sa = sb + s * STG_BYTES;
        int kt = s * 32;
        CP_ASYNC16(sa + dA0, Asrc0 + kt);
        CP_ASYNC16(sa + dA1, Asrc1 + kt);
        CP_ASYNC16(sa + 10240 + dA0, Wsrc0 + kt);
        CP_ASYNC16(sa + 10240 + dA1, Wsrc1 + kt);
        CP_COMMIT();
    }

    float acc[2][8][4];
#pragma unroll
    for (int mi = 0; mi < 2; mi++)
#pragma unroll
        for (int ni = 0; ni < 8; ni++)
#pragma unroll
            for (int c = 0; c < 4; c++) acc[mi][ni][c] = 0.f;
    unsigned cf[2][8][2];

    for (int it = 0; it < 32; it++) {
        CP_WAIT2();
        __syncthreads();
        if (it + 3 < 32) {
            uint32_t sa = sb + ((it + 3) & 3) * STG_BYTES;
            int kt = (it + 3) * 32;
            CP_ASYNC16(sa + dA0, Asrc0 + kt);
            CP_ASYNC16(sa + dA1, Asrc1 + kt);
            CP_ASYNC16(sa + 10240 + dA0, Wsrc0 + kt);
            CP_ASYNC16(sa + 10240 + dA1, Wsrc1 + kt);
        }
        CP_COMMIT();

        uint32_t stg = sb + (it & 3) * STG_BYTES;
        uint32_t ab = stg + a_off;
        uint32_t bb = stg + b_off;

        if ((it & 1) == 0) {
#pragma unroll
            for (int mi = 0; mi < 2; mi++)
#pragma unroll
                for (int ni = 0; ni < 8; ni++) { cf[mi][ni][0] = 0u; cf[mi][ni][1] = 0u; }
        }
#pragma unroll
        for (int ks = 0; ks < 2; ks++) {
            unsigned a[2][4], b[4][4];
            LDSM_X4(a[0][0], a[0][1], a[0][2], a[0][3], ab + ks * 32);
            LDSM_X4(a[1][0], a[1][1], a[1][2], a[1][3], ab + 1280 + ks * 32);
            LDSM_X4(b[0][0], b[0][1], b[0][2], b[0][3], bb + ks * 32);
            LDSM_X4(b[1][0], b[1][1], b[1][2], b[1][3], bb + 1280 + ks * 32);
            LDSM_X4(b[2][0], b[2][1], b[2][2], b[2][3], bb + 2560 + ks * 32);
            LDSM_X4(b[3][0], b[3][1], b[3][2], b[3][3], bb + 3840 + ks * 32);
#pragma unroll
            for (int mi = 0; mi < 2; mi++)
#pragma unroll
                for (int p = 0; p < 4; p++) {
                    mma_f16acc(cf[mi][2 * p],     a[mi], &b[p][0]);
                    mma_f16acc(cf[mi][2 * p + 1], a[mi], &b[p][2]);
                }
        }
        if ((it & 1) == 1) {
#pragma unroll
            for (int mi = 0; mi < 2; mi++)
#pragma unroll
                for (int ni = 0; ni < 8; ni++) {
                    float2 f0 = __half22float2(*reinterpret_cast<__half2*>(&cf[mi][ni][0]));
                    float2 f1 = __half22float2(*reinterpret_cast<__half2*>(&cf[mi][ni][1]));
                    acc[mi][ni][0] += f0.x;
                    acc[mi][ni][1] += f0.y;
                    acc[mi][ni][2] += f1.x;
                    acc[mi][ni][3] += f1.y;
                }
        }
        // no bottom sync: next iter's top barrier orders stage reuse (4 stages deep)
    }

    // epilogue: v-dot of tanh(acc + bias)
    float rs[2][2] = {{0.f, 0.f}, {0.f, 0.f}};
#pragma unroll
    for (int mi = 0; mi < 2; mi++) {
        int mr0 = m0 + wm * 32 + mi * 16 + g;
        const float* bs0 = bias + (size_t)(mr0 / NN) * D2H;
        const float* bs1 = bias + (size_t)((mr0 + 8) / NN) * D2H;
#pragma unroll
        for (int ni = 0; ni < 8; ni++) {
            int col = d0 + wn * 64 + ni * 8 + tig * 2;
            float v0 = v[col], v1 = v[col + 1];
            rs[mi][0] += v0 * tanh_mufu(acc[mi][ni][0] + bs0[col])
                       + v1 * tanh_mufu(acc[mi][ni][1] + bs0[col + 1]);
            rs[mi][1] += v0 * tanh_mufu(acc[mi][ni][2] + bs1[col])
                       + v1 * tanh_mufu(acc[mi][ni][3] + bs1[col + 1]);
        }
    }
    __syncthreads();   // all warps done with smem stages before esum reuse
    float (*esum)[128] = reinterpret_cast<float (*)[128]>(smem);
#pragma unroll
    for (int mi = 0; mi < 2; mi++)
#pragma unroll
        for (int p = 0; p < 2; p++) {
            float s = rs[mi][p];
            s += __shfl_xor_sync(0xffffffffu, s, 1);
            s += __shfl_xor_sync(0xffffffffu, s, 2);
            if (tig == 0) esum[wn][wm * 32 + mi * 16 + p * 8 + g] = s;
        }
    __syncthreads();
    if (tid < 128)
        et_part[(size_t)blockIdx.x * (BB * NN) + m0 + tid] = esum[0][tid] + esum[1][tid];
}

// ============================================================================
// generic fp16 tensor-core GEMM for the small GEMMs (unchanged)
// ============================================================================
__global__ void __launch_bounds__(256)
gemm_h(const float* __restrict__ A, const float* __restrict__ W,
       const float* __restrict__ bias, const float* __restrict__ v,
       float* __restrict__ C, float* __restrict__ et_part,
       int M, int Nn, int K, int mode, int rpb) {
    __shared__ unsigned As[128][20];
    __shared__ unsigned Ws[128][20];
    __shared__ float esum[2][128];

    int tid = threadIdx.x;
    int wid = tid >> 5, lane = tid & 31;
    int g = lane >> 2, tig = lane & 3;
    int wm = wid & 3, wn = wid >> 2;
    int n0 = blockIdx.x * 128, m0 = blockIdx.y * 128;

    float acc[2][8][4];
#pragma unroll
    for (int mi = 0; mi < 2; mi++)
#pragma unroll
        for (int ni = 0; ni < 8; ni++)
#pragma unroll
            for (int c = 0; c < 4; c++) acc[mi][ni][c] = 0.f;

    unsigned cf[2][8][2];

    float4 abuf[4], wbuf[4];
#pragma unroll
    for (int t = 0; t < 4; t++) {
        int idx = tid + t * 256;
        int r = idx >> 3, c4 = idx & 7;
        abuf[t] = *reinterpret_cast<const float4*>(A + (size_t)(m0 + r) * K + c4 * 4);
        int gn = n0 + r;
        wbuf[t] = (gn < Nn)
            ? *reinterpret_cast<const float4*>(W + (size_t)gn * K + c4 * 4)
            : make_float4(0.f, 0.f, 0.f, 0.f);
    }

    for (int k0 = 0; k0 < K; k0 += 32) {
#pragma unroll
        for (int t = 0; t < 4; t++) {
            int idx = tid + t * 256;
            int r = idx >> 3, c4 = idx & 7;
            As[r][c4 * 2 + 0] = pack_h2(abuf[t].x, abuf[t].y);
            As[r][c4 * 2 + 1] = pack_h2(abuf[t].z, abuf[t].w);
            Ws[r][c4 * 2 + 0] = pack_h2(wbuf[t].x, wbuf[t].y);
            Ws[r][c4 * 2 + 1] = pack_h2(wbuf[t].z, wbuf[t].w);
        }
        __syncthreads();
        if (k0 + 32 < K) {
#pragma unroll
            for (int t = 0; t < 4; t++) {
                int idx = tid + t * 256;
                int r = idx >> 3, c4 = idx & 7;
                abuf[t] = *reinterpret_cast<const float4*>(
                    A + (size_t)(m0 + r) * K + k0 + 32 + c4 * 4);
                int gn = n0 + r;
                wbuf[t] = (gn < Nn)
                    ? *reinterpret_cast<const float4*>(W + (size_t)gn * K + k0 + 32 + c4 * 4)
                    : make_float4(0.f, 0.f, 0.f, 0.f);
            }
        }
        if (((k0 >> 5) & 1) == 0) {
#pragma unroll
            for (int mi = 0; mi < 2; mi++)
#pragma unroll
                for (int ni = 0; ni < 8; ni++) { cf[mi][ni][0] = 0u; cf[mi][ni][1] = 0u; }
        }
#pragma unroll
        for (int ks = 0; ks < 2; ks++) {
            unsigned a[2][4], b[8][2];
#pragma unroll
            for (int mi = 0; mi < 2; mi++) {
                int row = wm * 32 + mi * 16 + g;
                a[mi][0] = As[row][ks * 8 + tig];
                a[mi][1] = As[row + 8][ks * 8 + tig];
                a[mi][2] = As[row][ks * 8 + tig + 4];
                a[mi][3] = As[row + 8][ks * 8 + tig + 4];
            }
#pragma unroll
            for (int ni = 0; ni < 8; ni++) {
                int col = wn * 64 + ni * 8 + g;
                b[ni][0] = Ws[col][ks * 8 + tig];
                b[ni][1] = Ws[col][ks * 8 + tig + 4];
            }
#pragma unroll
            for (int mi = 0; mi < 2; mi++)
#pragma unroll
                for (int ni = 0; ni < 8; ni++) mma_f16acc(cf[mi][ni], a[mi], b[ni]);
        }
        if (((k0 >> 5) & 1) == 1) {
#pragma unroll
            for (int mi = 0; mi < 2; mi++)
#pragma unroll
                for (int ni = 0; ni < 8; ni++) {
                    float2 f0 = __half22float2(*reinterpret_cast<__half2*>(&cf[mi][ni][0]));
                    float2 f1 = __half22float2(*reinterpret_cast<__half2*>(&cf[mi][ni][1]));
                    acc[mi][ni][0] += f0.x;
                    acc[mi][ni][1] += f0.y;
                    acc[mi][ni][2] += f1.x;
                    acc[mi][ni][3] += f1.y;
                }
        }
        __syncthreads();
    }

    if (mode == 0) {
#pragma unroll
        for (int mi = 0; mi < 2; mi++) {
            int mr = m0 + wm * 32 + mi * 16 + g;
#pragma unroll
            for (int ni = 0; ni < 8; ni++) {
                int cc = n0 + wn * 64 + ni * 8 + tig * 2;
                if (cc < Nn) {
                    float bv = bias ? bias[cc] : 0.f;
                    C[(size_t)mr * Nn + cc] = acc[mi][ni][0] + bv;
                    C[(size_t)(mr + 8) * Nn + cc] = acc[mi][ni][2] + bv;
                }
                if (cc + 1 < Nn) {
                    float bv = bias ? bias[cc + 1] : 0.f;
                    C[(size_t)mr * Nn + cc + 1] = acc[mi][ni][1] + bv;
                    C[(size_t)(mr + 8) * Nn + cc + 1] = acc[mi][ni][3] + bv;
                }
            }
        }
    } else {
        float rs[2][2] = {{0.f, 0.f}, {0.f, 0.f}};
#pragma unroll
        for (int mi = 0; mi < 2; mi++) {
            int mr0 = m0 + wm * 32 + mi * 16 + g;
            int b0i = mr0 / rpb;
            int b1i = (mr0 + 8) / rpb;
#pragma unroll
            for (int ni = 0; ni < 8; ni++) {
                int col = n0 + wn * 64 + ni * 8 + tig * 2;
                float v0 = v[col], v1 = v[col + 1];
                const float* bs0 = bias + (size_t)b0i * Nn;
                const float* bs1 = bias + (size_t)b1i * Nn;
                rs[mi][0] += v0 * tanh_mufu(acc[mi][ni][0] + bs0[col])
                           + v1 * tanh_mufu(acc[mi][ni][1] + bs0[col + 1]);
                rs[mi][1] += v0 * tanh_mufu(acc[mi][ni][2] + bs1[col])
                           + v1 * tanh_mufu(acc[mi][ni][3] + bs1[col + 1]);
            }
        }
#pragma unroll
        for (int mi = 0; mi < 2; mi++)
#pragma unroll
            for (int p = 0; p < 2; p++) {
                float s = rs[mi][p];
                s += __shfl_xor_sync(0xffffffffu, s, 1);
                s += __shfl_xor_sync(0xffffffffu, s, 2);
                if (tig == 0) esum[wn][wm * 32 + mi * 16 + p * 8 + g] = s;
            }
        __syncthreads();
        if (tid < 128)
            et_part[(size_t)blockIdx.x * M + m0 + tid] = esum[0][tid] + esum[1][tid];
    }
}

__global__ void k_reduce_et(const float* __restrict__ part, float* __restrict__ et,
                            int M, int ndt) {
    int m = blockIdx.x * 256 + threadIdx.x;
    if (m >= M) return;
    float s = 0.f;
    for (int t = 0; t < ndt; t++) s += part[(size_t)t * M + m];
    et[m] = s;
}

// ---------------- small kernels -----------------------------------------
__global__ void k_cat1280(const float* __restrict__ xt, const float* __restrict__ cte) {
    int idx = blockIdx.x * blockDim.x + threadIdx.x;
    if (idx >= BB * 1280) return;
    int b = idx / 1280, j = idx % 1280;
    g_cat1280[idx] = (j < EE) ? xt[b * EE + j] : cte[b * D2H + (j - EE)];
}

__global__ void k_cat768(const float* __restrict__ dec_h) {
    int idx = blockIdx.x * blockDim.x + threadIdx.x;
    if (idx >= BB * 768) return;
    int b = idx / 768, j = idx % 768;
    g_cat768[idx] = (j < EE) ? g_x[b * EE + j] : dec_h[b * HH + (j - EE)];
}

__global__ void k_w768(const float* __restrict__ wih, const float* __restrict__ whh) {
    int idx = blockIdx.x * blockDim.x + threadIdx.x;
    if (idx >= H4 * 768) return;
    int r = idx / 768, j = idx % 768;
    g_w768[idx] = (j < EE) ? wih[r * EE + j] : whh[r * HH + (j - EE)];
}

__global__ void k_lstm(const float* __restrict__ dec_c, const float* __restrict__ bih,
                       const float* __restrict__ bhh, float* __restrict__ out_h,
                       float* __restrict__ out_c, float* __restrict__ out_prevs) {
    int idx = blockIdx.x * blockDim.x + threadIdx.x;
    if (idx >= BB * HH) return;
    int b = idx >> 9, h = idx & 511;
    const float* g = &g_gates[b * H4];
    float gi = g[h] + bih[h] + bhh[h];
    float gf = g[HH + h] + bih[HH + h] + bhh[HH + h];
    float gg = g[2 * HH + h] + bih[2 * HH + h] + bhh[2 * HH + h];
    float go = g[3 * HH + h] + bih[3 * HH + h] + bhh[3 * HH + h];
    float c = (1.0f / (1.0f + expf(-gf))) * dec_c[idx]
            + (1.0f / (1.0f + expf(-gi))) * tanhf(gg);
    float hn = (1.0f / (1.0f + expf(-go))) * tanhf(c);
    out_h[idx] = hn;
    out_c[idx] = c;
    g_sthat[b * D2H + h] = hn;
    g_sthat[b * D2H + HH + h] = c;
    out_prevs[(size_t)b * (TT + 1) * HH + (size_t)TT * HH + h] = hn;
}

__global__ void k_copy_prevs(const float* __restrict__ prev_s, float* __restrict__ outp) {
    int idx = blockIdx.x * blockDim.x + threadIdx.x;
    if (idx >= BB * TT * HH) return;
    int b = idx / (TT * HH);
    int r = idx % (TT * HH);
    outp[(size_t)b * (TT + 1) * HH + r] = prev_s[idx];
}

__global__ void k_attn_enc(const float* __restrict__ mask, const float* __restrict__ sumt,
                           float* __restrict__ out_sumnew) {
    int b = blockIdx.x;
    int tid = threadIdx.x;
    __shared__ float sred[512];
    float atv = 0.f;
    if (tid < NN) {
        int idx = b * NN + tid;
        float e = __expf(g_et[idx]);
        out_sumnew[idx] = sumt[idx] + e;
        atv = (e / sumt[idx]) * mask[idx];
    }
    sred[tid] = atv;
    __syncthreads();
    for (int s = 256; s >= 1; s >>= 1) {
        if (tid < s) sred[tid] += sred[tid + s];
        __syncthreads();
    }
    float tot = sred[0];
    if (tid < NN) g_at[b * NN + tid] = atv / tot;
}

__global__ void k_cte(const float* __restrict__ enc_out, float* __restrict__ out_cte) {
    int b = blockIdx.x;
    int d = blockIdx.y * 256 + threadIdx.x;
    const float* at = &g_at[b * NN];
    const float* e = enc_out + (size_t)b * NN * D2H + d;
    float s = 0.f;
#pragma unroll 4
    for (int n = 0; n < NN; n++) s += at[n] * e[(size_t)n * D2H];
    out_cte[b * D2H + d] = s;
}

__global__ void k_attn_dec() {
    int b = blockIdx.x;
    int tid = threadIdx.x;
    __shared__ float sm[64];
    float v = (tid < TT) ? g_etd[b * TT + tid] : -1e30f;
    sm[tid] = v;
    __syncthreads();
    for (int s = 32; s >= 1; s >>= 1) {
        if (tid < s) sm[tid] = fmaxf(sm[tid], sm[tid + s]);
        __syncthreads();
    }
    float mx = sm[0];
    __syncthreads();
    float e = (tid < TT) ? __expf(v - mx) : 0.f;
    sm[tid] = e;
    __syncthreads();
    for (int s = 32; s >= 1; s >>= 1) {
        if (tid < s) sm[tid] += sm[tid + s];
        __syncthreads();
    }
    float tot = sm[0];
    if (tid < TT) g_atd[b * TT + tid] = e / tot;
}

__global__ void k_ctd(const float* __restrict__ prev_s) {
    int b = blockIdx.x;
    int h = blockIdx.y * 256 + threadIdx.x;
    float s = 0.f;
#pragma unroll
    for (int t = 0; t < TT; t++) s += g_atd[b * TT + t] * prev_s[((size_t)b * TT + t) * HH + h];
    g_ctd[b * HH + h] = s;
}

__global__ void k_cat2816(const float* __restrict__ cte_new) {
    int idx = blockIdx.x * blockDim.x + threadIdx.x;
    if (idx >= BB * 2816) return;
    int b = idx / 2816, j = idx % 2816;
    float v;
    if (j < 1024) v = cte_new[b * D2H + j];
    else if (j < 1536) v = g_ctd[b * HH + (j - 1024)];
    else if (j < 2560) v = g_sthat[b * D2H + (j - 1536)];
    else v = g_x[b * EE + (j - 2560)];
    g_cat2816[idx] = v;
}

__global__ void k_pgen(const float* __restrict__ pw, const float* __restrict__ pb) {
    int b = blockIdx.x;
    int tid = threadIdx.x;
    __shared__ float sr[256];
    float s = 0.f;
    for (int j = tid; j < 2816; j += 256) s += pw[j] * g_cat2816[b * 2816 + j];
    sr[tid] = s;
    __syncthreads();
    for (int st = 128; st >= 1; st >>= 1) {
        if (tid < st) sr[tid] += sr[tid + st];
        __syncthreads();
    }
    if (tid == 0) g_pgen[b] = 1.0f / (1.0f + expf(-(sr[0] + pb[0])));
}

__global__ void k_cat2048(const float* __restrict__ out_h, const float* __restrict__ cte_new) {
    int idx = blockIdx.x * blockDim.x + threadIdx.x;
    if (idx >= BB * H4) return;
    int b = idx / H4, j = idx % H4;
    float v;
    if (j < 512) v = out_h[b * HH + j];
    else if (j < 1536) v = cte_new[b * D2H + (j - 512)];
    else v = g_ctd[b * HH + (j - 1536)];
    g_cat2048[idx] = v;
}

__global__ void k_vocab(const float* __restrict__ extra, float* __restrict__ out_final) {
    int b = blockIdx.x;
    int tid = threadIdx.x;
    __shared__ float sr[1024];
    const float* lg = &g_logits[(size_t)b * VV];
    float mx = -1e30f;
    for (int v = tid; v < VV; v += 1024) mx = fmaxf(mx, lg[v]);
    sr[tid] = mx;
    __syncthreads();
    for (int s = 512; s >= 1; s >>= 1) {
        if (tid < s) sr[tid] = fmaxf(sr[tid], sr[tid + s]);
        __syncthreads();
    }
    mx = sr[0];
    __syncthreads();
    float sum = 0.f;
    for (int v = tid; v < VV; v += 1024) sum += __expf(lg[v] - mx);
    sr[tid] = sum;
    __syncthreads();
    for (int s = 512; s >= 1; s >>= 1) {
        if (tid < s) sr[tid] += sr[tid + s];
        __syncthreads();
    }
    float scale = g_pgen[b] / sr[0];
    float* fb = out_final + (size_t)b * (VV + OOV);
    for (int v = tid; v < VV; v += 1024) fb[v] = __expf(lg[v] - mx) * scale;
    for (int j = tid; j < OOV; j += 1024) fb[VV + j] = extra[b * OOV + j];
}

__global__ void k_scatter(const int* __restrict__ ebev, float* __restrict__ out_final) {
    int idx = blockIdx.x * blockDim.x + threadIdx.x;
    if (idx >= BB * NN) return;
    int b = idx / NN;
    float w = (1.f - g_pgen[b]) * g_at[idx];
    atomicAdd(&out_final[(size_t)b * (VV + OOV) + ebev[idx]], w);
}

// ---------------- host ---------------------------------------------------
static void* sym(const void* s) {
    void* p = nullptr;
    cudaGetSymbolAddress(&p, s);
    return p;
}

extern "C" void kernel_launch(void* const* d_in, const int* in_sizes, int n_in,
                              void* d_out, int out_size) {
    const float* x_t   = (const float*)d_in[0];
    const float* dec_h = (const float*)d_in[1];
    const float* dec_c = (const float*)d_in[2];
    const float* enc_out = (const float*)d_in[3];
    const float* enc_mask = (const float*)d_in[4];
    const float* ct_e = (const float*)d_in[5];
    const float* extra_zeros = (const float*)d_in[6];
    const int*   ebev = (const int*)d_in[7];
    const float* sum_temporal = (const float*)d_in[8];
    const float* prev_s = (const float*)d_in[9];
    const float* x_input_w = (const float*)d_in[10];
    const float* x_input_b = (const float*)d_in[11];
    const float* lstm_w_ih = (const float*)d_in[12];
    const float* lstm_w_hh = (const float*)d_in[13];
    const float* lstm_b_ih = (const float*)d_in[14];
    const float* lstm_b_hh = (const float*)d_in[15];
    const float* pgen_w = (const float*)d_in[16];
    const float* pgen_b = (const float*)d_in[17];
    const float* V_w = (const float*)d_in[18];
    const float* V_b = (const float*)d_in[19];
    const float* V1_w = (const float*)d_in[20];
    const float* V1_b = (const float*)d_in[21];
    const float* Wh_w = (const float*)d_in[22];
    const float* Ws_w = (const float*)d_in[23];
    const float* Ws_b = (const float*)d_in[24];
    const float* v_w = (const float*)d_in[25];
    const float* Wprev_w = (const float*)d_in[26];
    const float* Wsd_w = (const float*)d_in[27];
    const float* Wsd_b = (const float*)d_in[28];
    const float* vd_w = (const float*)d_in[29];

    float* out = (float*)d_out;
    float* out_final = out;
    float* out_h = out_final + (size_t)BB * (VV + OOV);
    float* out_c = out_h + (size_t)BB * HH;
    float* out_cte = out_c + (size_t)BB * HH;
    float* out_sumnew = out_cte + (size_t)BB * D2H;
    float* out_prevs = out_sumnew + (size_t)BB * NN;

    float* p_cat1280 = (float*)sym(g_cat1280);
    float* p_x = (float*)sym(g_x);
    float* p_cat768 = (float*)sym(g_cat768);
    float* p_w768 = (float*)sym(g_w768);
    float* p_gates = (float*)sym(g_gates);
    float* p_sthat = (float*)sym(g_sthat);
    float* p_sdec = (float*)sym(g_sdec);
    float* p_hdec = (float*)sym(g_hdec);
    float* p_et = (float*)sym(g_et);
    float* p_etd = (float*)sym(g_etd);
    float* p_cat2048 = (float*)sym(g_cat2048);
    float* p_out2 = (float*)sym(g_out2);
    float* p_logits = (float*)sym(g_logits);
    float* p_etpart = (float*)sym(g_etpart);
    const __half* p_ench = (const __half*)sym(g_ench);
    const __half* p_wh16 = (const __half*)sym(g_wh16);

    static bool attr_done = false;
    if (!attr_done) {
        cudaFuncSetAttribute(attn16, cudaFuncAttributeMaxDynamicSharedMemorySize, 4 * STG_BYTES);
        attr_done = true;
    }

    // 0) pre-convert enc_out + Wh to fp16 (one pass)
    k_cvt<<<(ENC4 + WH4 + 255) / 256, 256>>>(enc_out, Wh_w);

    // 1) x = Linear(cat(x_t, ct_e))
    k_cat1280<<<(BB * 1280 + 255) / 256, 256>>>(x_t, ct_e);
    gemm_h<<<dim3(2, 2), 256>>>(p_cat1280, x_input_w, x_input_b, nullptr,
                                p_x, nullptr, BB, EE, 1280, 0, 1);

    // 2) LSTM gates + cell
    k_cat768<<<(BB * 768 + 255) / 256, 256>>>(dec_h);
    k_w768<<<(H4 * 768 + 255) / 256, 256>>>(lstm_w_ih, lstm_w_hh);
    gemm_h<<<dim3(16, 2), 256>>>(p_cat768, p_w768, nullptr, nullptr,
                                 p_gates, nullptr, BB, H4, 768, 0, 1);
    k_lstm<<<(BB * HH + 255) / 256, 256>>>(dec_c, lstm_b_ih, lstm_b_hh, out_h, out_c, out_prevs);
    k_copy_prevs<<<(BB * TT * HH + 255) / 256, 256>>>(prev_s, out_prevs);

    // 3) attention projections
    gemm_h<<<dim3(8, 2), 256>>>(p_sthat, Ws_w, Ws_b, nullptr,
                                p_sdec, nullptr, BB, D2H, D2H, 0, 1);
    gemm_h<<<dim3(4, 2), 256>>>(out_h, Wsd_w, Wsd_b, nullptr,
                                p_hdec, nullptr, BB, HH, HH, 0, 1);

    // 4) encoder intra-temporal attention — fp16 ldmatrix pipelined kernel
    attn16<<<dim3(8, 800), 256, 4 * STG_BYTES>>>(p_ench, p_wh16, p_sdec, v_w, p_etpart);
    k_reduce_et<<<(BB * NN + 255) / 256, 256>>>(p_etpart, p_et, BB * NN, 8);
    k_attn_enc<<<BB, 512>>>(enc_mask, sum_temporal, out_sumnew);
    k_cte<<<dim3(BB, 4), 256>>>(enc_out, out_cte);

    // 5) intra-decoder attention
    gemm_h<<<dim3(4, 98), 256>>>(prev_s, Wprev_w, p_hdec, vd_w,
                                 nullptr, p_etpart, BB * TT, HH, HH, 1, TT);
    k_reduce_et<<<(BB * TT + 255) / 256, 256>>>(p_etpart, p_etd, BB * TT, 4);
    k_attn_dec<<<BB, 64>>>();
    k_ctd<<<dim3(BB, 2), 256>>>(prev_s);

    // 6) pointer-generator
    k_cat2816<<<(BB * 2816 + 255) / 256, 256>>>(out_cte);
    k_pgen<<<BB, 256>>>(pgen_w, pgen_b);
    k_cat2048<<<(BB * H4 + 255) / 256, 256>>>(out_h, out_cte);
    gemm_h<<<dim3(4, 2), 256>>>(p_cat2048, V_w, V_b, nullptr,
                                p_out2, nullptr, BB, HH, H4, 0, 1);
    gemm_h<<<dim3(391, 2), 256>>>(p_out2, V1_w, V1_b, nullptr,
                                  p_logits, nullptr, BB, VV, HH, 0, 1);

    // 7) final distribution
    k_vocab<<<BB, 1024>>>(extra_zeros, out_final);
    k_scatter<<<(BB * NN + 255) / 256, 256>>>(ebev, out_final);
}

// round 11
// speedup vs baseline: 1.0672x; 1.0672x over previous
#include <cuda_runtime.h>
#include <cuda_fp16.h>
#include <cstdint>

// Problem constants
#define BB 256
#define NN 400
#define HH 512
#define EE 256
#define VV 50000
#define OOV 50
#define TT 49
#define D2H 1024   // 2*H
#define H4 2048    // 4*H
#define NB 128     // batches per chunk (2 chunks)

// ---------------- scratch (static device globals; no runtime alloc) -------
__device__ float g_cat1280[BB * 1280];
__device__ float g_x[BB * EE];
__device__ float g_cat768[BB * 768];
__device__ float g_w768[H4 * 768];
__device__ float g_gates[BB * H4];
__device__ float g_sthat[BB * D2H];
__device__ float g_sdec[BB * D2H];
__device__ float g_hdec[BB * HH];
__device__ float g_et[BB * NN];
__device__ float g_at[BB * NN];
__device__ float g_etd[BB * TT];
__device__ float g_atd[BB * TT];
__device__ float g_ctd[BB * HH];
__device__ float g_cat2816[BB * 2816];
__device__ float g_pgen[BB];
__device__ float g_cat2048[BB * H4];
__device__ float g_out2[BB * HH];
__device__ float g_logits[(size_t)BB * VV];
__device__ float g_etpart[8 * BB * NN];      // enc-attn partials
__device__ float g_etpartd[4 * BB * TT];     // dec-attn partials (separate: runs concurrently)
__device__ __half g_ench[(size_t)BB * NN * D2H];   // enc_out in fp16 (210MB)
__device__ __half g_wh16[D2H * D2H];               // Wh in fp16

__device__ __forceinline__ float tanh_mufu(float x) {
    float y;
    asm("tanh.approx.f32 %0, %1;" : "=f"(y) : "f"(x));
    return y;
}

__device__ __forceinline__ unsigned pack_h2(float a, float b) {
    __half2 h = __floats2half2_rn(a, b);
    return *reinterpret_cast<unsigned*>(&h);
}

__device__ __forceinline__ uint32_t smem_u32(const void* p) {
    uint32_t a;
    asm("{ .reg .u64 t; cvta.to.shared.u64 t, %1; cvt.u32.u64 %0, t; }" : "=r"(a) : "l"(p));
    return a;
}

#define CP_ASYNC16(dst, src) \
    asm volatile("cp.async.cg.shared.global [%0], [%1], 16;" :: "r"(dst), "l"(src) : "memory")
#define CP_COMMIT() asm volatile("cp.async.commit_group;" ::: "memory")
#define CP_WAIT2()  asm volatile("cp.async.wait_group 2;" ::: "memory")

// fp16-accumulate MMA: C(f16x2 x2) += A x B
__device__ __forceinline__ void mma_f16acc(unsigned* c, const unsigned* a, const unsigned* b) {
    asm volatile(
        "mma.sync.aligned.m16n8k16.row.col.f16.f16.f16.f16 "
        "{%0,%1}, {%2,%3,%4,%5}, {%6,%7}, {%0,%1};\n"
        : "+r"(c[0]), "+r"(c[1])
        : "r"(a[0]), "r"(a[1]), "r"(a[2]), "r"(a[3]), "r"(b[0]), "r"(b[1]));
}

// ---------------- fp32->fp16 pre-convert (enc_out + Wh) -------------------
#define ENC4 (BB * NN * D2H / 4)
#define WH4  (D2H * D2H / 4)
__global__ void k_cvt(const float* __restrict__ enc, const float* __restrict__ wh) {
    int i = blockIdx.x * 256 + threadIdx.x;
    if (i >= ENC4 + WH4) return;
    float4 v;
    __half2* dst;
    if (i < ENC4) {
        v = reinterpret_cast<const float4*>(enc)[i];
        dst = reinterpret_cast<__half2*>(g_ench + (size_t)i * 4);
    } else {
        v = reinterpret_cast<const float4*>(wh)[i - ENC4];
        dst = reinterpret_cast<__half2*>(g_wh16 + (size_t)(i - ENC4) * 4);
    }
    dst[0] = __floats2half2_rn(v.x, v.y);
    dst[1] = __floats2half2_rn(v.z, v.w);
}

// ============================================================================
// Big attention-score kernel (R9-proven loop): fp16 inputs, cp.async 4-stage,
// scalar-LDS fragment loads, f16 MMA accumulation (K=64 split -> f32).
// Block tile 128(M) x 128(N) x 32(K), 32 k-iters. grid (8, 400) per chunk.
// ============================================================================
#define STG_BYTES 20480
__global__ void __launch_bounds__(256, 1)
attn16(const __half* __restrict__ A, const __half* __restrict__ W,
       const float* __restrict__ bias, const float* __restrict__ v,
       float* __restrict__ et_part, int m_base) {
    extern __shared__ __align__(16) char smem[];
    uint32_t sb = smem_u32(smem);

    int tid = threadIdx.x;
    int wid = tid >> 5, lane = tid & 31;
    int g = lane >> 2, tig = lane & 3;
    int wm = wid & 3, wn = wid >> 2;
    int d0 = blockIdx.x * 128, m0 = m_base + blockIdx.y * 128;

    int r0 = tid >> 2, c0 = tid & 3;
    int r1 = (tid + 256) >> 2;
    const __half* Asrc0 = A + (size_t)(m0 + r0) * D2H + c0 * 8;
    const __half* Asrc1 = A + (size_t)(m0 + r1) * D2H + c0 * 8;
    const __half* Wsrc0 = W + (size_t)(d0 + r0) * D2H + c0 * 8;
    const __half* Wsrc1 = W + (size_t)(d0 + r1) * D2H + c0 * 8;
    uint32_t dA0 = r0 * 80 + c0 * 16, dA1 = r1 * 80 + c0 * 16;

    // prologue: fill stages 0..2
#pragma unroll
    for (int s = 0; s < 3; s++) {
        uint32_t sa = sb + s * STG_BYTES;
        int kt = s * 32;
        CP_ASYNC16(sa + dA0, Asrc0 + kt);
        CP_ASYNC16(sa + dA1, Asrc1 + kt);
        CP_ASYNC16(sa + 10240 + dA0, Wsrc0 + kt);
        CP_ASYNC16(sa + 10240 + dA1, Wsrc1 + kt);
        CP_COMMIT();
    }

    float acc[2][8][4];
#pragma unroll
    for (int mi = 0; mi < 2; mi++)
#pragma unroll
        for (int ni = 0; ni < 8; ni++)
#pragma unroll
            for (int c = 0; c < 4; c++) acc[mi][ni][c] = 0.f;
    unsigned cf[2][8][2];

    for (int it = 0; it < 32; it++) {
        CP_WAIT2();
        __syncthreads();
        if (it + 3 < 32) {
            uint32_t sa = sb + ((it + 3) & 3) * STG_BYTES;
            int kt = (it + 3) * 32;
            CP_ASYNC16(sa + dA0, Asrc0 + kt);
            CP_ASYNC16(sa + dA1, Asrc1 + kt);
            CP_ASYNC16(sa + 10240 + dA0, Wsrc0 + kt);
            CP_ASYNC16(sa + 10240 + dA1, Wsrc1 + kt);
        }
        CP_COMMIT();

        const uint32_t* Aw = reinterpret_cast<const uint32_t*>(smem + (it & 3) * STG_BYTES);
        const uint32_t* Ww = Aw + 2560;

        if ((it & 1) == 0) {
#pragma unroll
            for (int mi = 0; mi < 2; mi++)
#pragma unroll
                for (int ni = 0; ni < 8; ni++) { cf[mi][ni][0] = 0u; cf[mi][ni][1] = 0u; }
        }
#pragma unroll
        for (int ks = 0; ks < 2; ks++) {
            unsigned a[2][4], b[8][2];
#pragma unroll
            for (int mi = 0; mi < 2; mi++) {
                int row = wm * 32 + mi * 16 + g;
                a[mi][0] = Aw[row * 20 + ks * 8 + tig];
                a[mi][1] = Aw[(row + 8) * 20 + ks * 8 + tig];
                a[mi][2] = Aw[row * 20 + ks * 8 + tig + 4];
                a[mi][3] = Aw[(row + 8) * 20 + ks * 8 + tig + 4];
            }
#pragma unroll
            for (int ni = 0; ni < 8; ni++) {
                int col = wn * 64 + ni * 8 + g;
                b[ni][0] = Ww[col * 20 + ks * 8 + tig];
                b[ni][1] = Ww[col * 20 + ks * 8 + tig + 4];
            }
#pragma unroll
            for (int mi = 0; mi < 2; mi++)
#pragma unroll
                for (int ni = 0; ni < 8; ni++) mma_f16acc(cf[mi][ni], a[mi], b[ni]);
        }
        if ((it & 1) == 1) {
#pragma unroll
            for (int mi = 0; mi < 2; mi++)
#pragma unroll
                for (int ni = 0; ni < 8; ni++) {
                    float2 f0 = __half22float2(*reinterpret_cast<__half2*>(&cf[mi][ni][0]));
                    float2 f1 = __half22float2(*reinterpret_cast<__half2*>(&cf[mi][ni][1]));
                    acc[mi][ni][0] += f0.x;
                    acc[mi][ni][1] += f0.y;
                    acc[mi][ni][2] += f1.x;
                    acc[mi][ni][3] += f1.y;
                }
        }
        __syncthreads();
    }

    // epilogue: v-dot of tanh(acc + bias)
    float rs[2][2] = {{0.f, 0.f}, {0.f, 0.f}};
#pragma unroll
    for (int mi = 0; mi < 2; mi++) {
        int mr0 = m0 + wm * 32 + mi * 16 + g;
        const float* bs0 = bias + (size_t)(mr0 / NN) * D2H;
        const float* bs1 = bias + (size_t)((mr0 + 8) / NN) * D2H;
#pragma unroll
        for (int ni = 0; ni < 8; ni++) {
            int col = d0 + wn * 64 + ni * 8 + tig * 2;
            float v0 = v[col], v1 = v[col + 1];
            rs[mi][0] += v0 * tanh_mufu(acc[mi][ni][0] + bs0[col])
                       + v1 * tanh_mufu(acc[mi][ni][1] + bs0[col + 1]);
            rs[mi][1] += v0 * tanh_mufu(acc[mi][ni][2] + bs1[col])
                       + v1 * tanh_mufu(acc[mi][ni][3] + bs1[col + 1]);
        }
    }
    float (*esum)[128] = reinterpret_cast<float (*)[128]>(smem);
#pragma unroll
    for (int mi = 0; mi < 2; mi++)
#pragma unroll
        for (int p = 0; p < 2; p++) {
            float s = rs[mi][p];
            s += __shfl_xor_sync(0xffffffffu, s, 1);
            s += __shfl_xor_sync(0xffffffffu, s, 2);
            if (tig == 0) esum[wn][wm * 32 + mi * 16 + p * 8 + g] = s;
        }
    __syncthreads();
    if (tid < 128)
        et_part[(size_t)blockIdx.x * (BB * NN) + m0 + tid] = esum[0][tid] + esum[1][tid];
}

// ============================================================================
// generic fp16 tensor-core GEMM for the small GEMMs (unchanged)
// ============================================================================
__global__ void __launch_bounds__(256)
gemm_h(const float* __restrict__ A, const float* __restrict__ W,
       const float* __restrict__ bias, const float* __restrict__ v,
       float* __restrict__ C, float* __restrict__ et_part,
       int M, int Nn, int K, int mode, int rpb) {
    __shared__ unsigned As[128][20];
    __shared__ unsigned Ws[128][20];
    __shared__ float esum[2][128];

    int tid = threadIdx.x;
    int wid = tid >> 5, lane = tid & 31;
    int g = lane >> 2, tig = lane & 3;
    int wm = wid & 3, wn = wid >> 2;
    int n0 = blockIdx.x * 128, m0 = blockIdx.y * 128;

    float acc[2][8][4];
#pragma unroll
    for (int mi = 0; mi < 2; mi++)
#pragma unroll
        for (int ni = 0; ni < 8; ni++)
#pragma unroll
            for (int c = 0; c < 4; c++) acc[mi][ni][c] = 0.f;

    unsigned cf[2][8][2];

    float4 abuf[4], wbuf[4];
#pragma unroll
    for (int t = 0; t < 4; t++) {
        int idx = tid + t * 256;
        int r = idx >> 3, c4 = idx & 7;
        abuf[t] = *reinterpret_cast<const float4*>(A + (size_t)(m0 + r) * K + c4 * 4);
        int gn = n0 + r;
        wbuf[t] = (gn < Nn)
            ? *reinterpret_cast<const float4*>(W + (size_t)gn * K + c4 * 4)
            : make_float4(0.f, 0.f, 0.f, 0.f);
    }

    for (int k0 = 0; k0 < K; k0 += 32) {
#pragma unroll
        for (int t = 0; t < 4; t++) {
            int idx = tid + t * 256;
            int r = idx >> 3, c4 = idx & 7;
            As[r][c4 * 2 + 0] = pack_h2(abuf[t].x, abuf[t].y);
            As[r][c4 * 2 + 1] = pack_h2(abuf[t].z, abuf[t].w);
            Ws[r][c4 * 2 + 0] = pack_h2(wbuf[t].x, wbuf[t].y);
            Ws[r][c4 * 2 + 1] = pack_h2(wbuf[t].z, wbuf[t].w);
        }
        __syncthreads();
        if (k0 + 32 < K) {
#pragma unroll
            for (int t = 0; t < 4; t++) {
                int idx = tid + t * 256;
                int r = idx >> 3, c4 = idx & 7;
                abuf[t] = *reinterpret_cast<const float4*>(
                    A + (size_t)(m0 + r) * K + k0 + 32 + c4 * 4);
                int gn = n0 + r;
                wbuf[t] = (gn < Nn)
                    ? *reinterpret_cast<const float4*>(W + (size_t)gn * K + k0 + 32 + c4 * 4)
                    : make_float4(0.f, 0.f, 0.f, 0.f);
            }
        }
        if (((k0 >> 5) & 1) == 0) {
#pragma unroll
            for (int mi = 0; mi < 2; mi++)
#pragma unroll
                for (int ni = 0; ni < 8; ni++) { cf[mi][ni][0] = 0u; cf[mi][ni][1] = 0u; }
        }
#pragma unroll
        for (int ks = 0; ks < 2; ks++) {
            unsigned a[2][4], b[8][2];
#pragma unroll
            for (int mi = 0; mi < 2; mi++) {
                int row = wm * 32 + mi * 16 + g;
                a[mi][0] = As[row][ks * 8 + tig];
                a[mi][1] = As[row + 8][ks * 8 + tig];
                a[mi][2] = As[row][ks * 8 + tig + 4];
                a[mi][3] = As[row + 8][ks * 8 + tig + 4];
            }
#pragma unroll
            for (int ni = 0; ni < 8; ni++) {
                int col = wn * 64 + ni * 8 + g;
                b[ni][0] = Ws[col][ks * 8 + tig];
                b[ni][1] = Ws[col][ks * 8 + tig + 4];
            }
#pragma unroll
            for (int mi = 0; mi < 2; mi++)
#pragma unroll
                for (int ni = 0; ni < 8; ni++) mma_f16acc(cf[mi][ni], a[mi], b[ni]);
        }
        if (((k0 >> 5) & 1) == 1) {
#pragma unroll
            for (int mi = 0; mi < 2; mi++)
#pragma unroll
                for (int ni = 0; ni < 8; ni++) {
                    float2 f0 = __half22float2(*reinterpret_cast<__half2*>(&cf[mi][ni][0]));
                    float2 f1 = __half22float2(*reinterpret_cast<__half2*>(&cf[mi][ni][1]));
                    acc[mi][ni][0] += f0.x;
                    acc[mi][ni][1] += f0.y;
                    acc[mi][ni][2] += f1.x;
                    acc[mi][ni][3] += f1.y;
                }
        }
        __syncthreads();
    }

    if (mode == 0) {
#pragma unroll
        for (int mi = 0; mi < 2; mi++) {
            int mr = m0 + wm * 32 + mi * 16 + g;
            if (mr >= M) continue;
#pragma unroll
            for (int ni = 0; ni < 8; ni++) {
                int cc = n0 + wn * 64 + ni * 8 + tig * 2;
                if (cc < Nn) {
                    float bv = bias ? bias[cc] : 0.f;
                    C[(size_t)mr * Nn + cc] = acc[mi][ni][0] + bv;
                    if (mr + 8 < M) C[(size_t)(mr + 8) * Nn + cc] = acc[mi][ni][2] + bv;
                }
                if (cc + 1 < Nn) {
                    float bv = bias ? bias[cc + 1] : 0.f;
                    C[(size_t)mr * Nn + cc + 1] = acc[mi][ni][1] + bv;
                    if (mr + 8 < M) C[(size_t)(mr + 8) * Nn + cc + 1] = acc[mi][ni][3] + bv;
                }
            }
        }
    } else {
        float rs[2][2] = {{0.f, 0.f}, {0.f, 0.f}};
#pragma unroll
        for (int mi = 0; mi < 2; mi++) {
            int mr0 = m0 + wm * 32 + mi * 16 + g;
            int b0i = mr0 / rpb;
            int b1i = (mr0 + 8) / rpb;
#pragma unroll
            for (int ni = 0; ni < 8; ni++) {
                int col = n0 + wn * 64 + ni * 8 + tig * 2;
                float v0 = v[col], v1 = v[col + 1];
                const float* bs0 = bias + (size_t)b0i * Nn;
                const float* bs1 = bias + (size_t)b1i * Nn;
                rs[mi][0] += v0 * tanh_mufu(acc[mi][ni][0] + bs0[col])
                           + v1 * tanh_mufu(acc[mi][ni][1] + bs0[col + 1]);
                rs[mi][1] += v0 * tanh_mufu(acc[mi][ni][2] + bs1[col])
                           + v1 * tanh_mufu(acc[mi][ni][3] + bs1[col + 1]);
            }
        }
#pragma unroll
        for (int mi = 0; mi < 2; mi++)
#pragma unroll
            for (int p = 0; p < 2; p++) {
                float s = rs[mi][p];
                s += __shfl_xor_sync(0xffffffffu, s, 1);
                s += __shfl_xor_sync(0xffffffffu, s, 2);
                if (tig == 0) esum[wn][wm * 32 + mi * 16 + p * 8 + g] = s;
            }
        __syncthreads();
        if (tid < 128)
            et_part[(size_t)blockIdx.x * M + m0 + tid] = esum[0][tid] + esum[1][tid];
    }
}

__global__ void k_reduce_et(const float* __restrict__ part, float* __restrict__ et,
                            int stride, int base, int count, int ndt) {
    int i = blockIdx.x * 256 + threadIdx.x;
    if (i >= count) return;
    int m = base + i;
    float s = 0.f;
    for (int t = 0; t < ndt; t++) s += part[(size_t)t * stride + m];
    et[m] = s;
}

// ---------------- small kernels -----------------------------------------
__global__ void k_cat1280(const float* __restrict__ xt, const float* __restrict__ cte) {
    int idx = blockIdx.x * blockDim.x + threadIdx.x;
    if (idx >= BB * 1280) return;
    int b = idx / 1280, j = idx % 1280;
    g_cat1280[idx] = (j < EE) ? xt[b * EE + j] : cte[b * D2H + (j - EE)];
}

__global__ void k_cat768(const float* __restrict__ dec_h) {
    int idx = blockIdx.x * blockDim.x + threadIdx.x;
    if (idx >= BB * 768) return;
    int b = idx / 768, j = idx % 768;
    g_cat768[idx] = (j < EE) ? g_x[b * EE + j] : dec_h[b * HH + (j - EE)];
}

__global__ void k_w768(const float* __restrict__ wih, const float* __restrict__ whh) {
    int idx = blockIdx.x * blockDim.x + threadIdx.x;
    if (idx >= H4 * 768) return;
    int r = idx / 768, j = idx % 768;
    g_w768[idx] = (j < EE) ? wih[r * EE + j] : whh[r * HH + (j - EE)];
}

__global__ void k_lstm(const float* __restrict__ dec_c, const float* __restrict__ bih,
                       const float* __restrict__ bhh, float* __restrict__ out_h,
                       float* __restrict__ out_c, float* __restrict__ out_prevs) {
    int idx = blockIdx.x * blockDim.x + threadIdx.x;
    if (idx >= BB * HH) return;
    int b = idx >> 9, h = idx & 511;
    const float* g = &g_gates[b * H4];
    float gi = g[h] + bih[h] + bhh[h];
    float gf = g[HH + h] + bih[HH + h] + bhh[HH + h];
    float gg = g[2 * HH + h] + bih[2 * HH + h] + bhh[2 * HH + h];
    float go = g[3 * HH + h] + bih[3 * HH + h] + bhh[3 * HH + h];
    float c = (1.0f / (1.0f + expf(-gf))) * dec_c[idx]
            + (1.0f / (1.0f + expf(-gi))) * tanhf(gg);
    float hn = (1.0f / (1.0f + expf(-go))) * tanhf(c);
    out_h[idx] = hn;
    out_c[idx] = c;
    g_sthat[b * D2H + h] = hn;
    g_sthat[b * D2H + HH + h] = c;
    out_prevs[(size_t)b * (TT + 1) * HH + (size_t)TT * HH + h] = hn;
}

__global__ void k_copy_prevs(const float* __restrict__ prev_s, float* __restrict__ outp) {
    int idx = blockIdx.x * blockDim.x + threadIdx.x;
    if (idx >= BB * TT * HH) return;
    int b = idx / (TT * HH);
    int r = idx % (TT * HH);
    outp[(size_t)b * (TT + 1) * HH + r] = prev_s[idx];
}

__global__ void k_attn_enc(const float* __restrict__ mask, const float* __restrict__ sumt,
                           float* __restrict__ out_sumnew, int b0) {
    int b = b0 + blockIdx.x;
    int tid = threadIdx.x;
    __shared__ float sred[512];
    float atv = 0.f;
    if (tid < NN) {
        int idx = b * NN + tid;
        float e = __expf(g_et[idx]);
        out_sumnew[idx] = sumt[idx] + e;
        atv = (e / sumt[idx]) * mask[idx];
    }
    sred[tid] = atv;
    __syncthreads();
    for (int s = 256; s >= 1; s >>= 1) {
        if (tid < s) sred[tid] += sred[tid + s];
        __syncthreads();
    }
    float tot = sred[0];
    if (tid < NN) g_at[b * NN + tid] = atv / tot;
}

// ct_e from fp16 enc copy (half the traffic)
__global__ void k_cte_h(float* __restrict__ out_cte, int b0) {
    int b = b0 + blockIdx.x;
    int d = blockIdx.y * 256 + threadIdx.x;
    const float* at = &g_at[b * NN];
    const __half* e = g_ench + (size_t)b * NN * D2H + d;
    float s = 0.f;
#pragma unroll 4
    for (int n = 0; n < NN; n++) s += at[n] * __half2float(e[(size_t)n * D2H]);
    out_cte[b * D2H + d] = s;
}

__global__ void k_attn_dec() {
    int b = blockIdx.x;
    int tid = threadIdx.x;
    __shared__ float sm[64];
    float v = (tid < TT) ? g_etd[b * TT + tid] : -1e30f;
    sm[tid] = v;
    __syncthreads();
    for (int s = 32; s >= 1; s >>= 1) {
        if (tid < s) sm[tid] = fmaxf(sm[tid], sm[tid + s]);
        __syncthreads();
    }
    float mx = sm[0];
    __syncthreads();
    float e = (tid < TT) ? __expf(v - mx) : 0.f;
    sm[tid] = e;
    __syncthreads();
    for (int s = 32; s >= 1; s >>= 1) {
        if (tid < s) sm[tid] += sm[tid + s];
        __syncthreads();
    }
    float tot = sm[0];
    if (tid < TT) g_atd[b * TT + tid] = e / tot;
}

__global__ void k_ctd(const float* __restrict__ prev_s) {
    int b = blockIdx.x;
    int h = blockIdx.y * 256 + threadIdx.x;
    float s = 0.f;
#pragma unroll
    for (int t = 0; t < TT; t++) s += g_atd[b * TT + t] * prev_s[((size_t)b * TT + t) * HH + h];
    g_ctd[b * HH + h] = s;
}

__global__ void k_cat2816(const float* __restrict__ cte_new, int b0) {
    int idx = blockIdx.x * blockDim.x + threadIdx.x;
    if (idx >= NB * 2816) return;
    int b = b0 + idx / 2816, j = idx % 2816;
    float v;
    if (j < 1024) v = cte_new[b * D2H + j];
    else if (j < 1536) v = g_ctd[b * HH + (j - 1024)];
    else if (j < 2560) v = g_sthat[b * D2H + (j - 1536)];
    else v = g_x[b * EE + (j - 2560)];
    g_cat2816[b * 2816 + j] = v;
}

__global__ void k_pgen(const float* __restrict__ pw, const float* __restrict__ pb, int b0) {
    int b = b0 + blockIdx.x;
    int tid = threadIdx.x;
    __shared__ float sr[256];
    float s = 0.f;
    for (int j = tid; j < 2816; j += 256) s += pw[j] * g_cat2816[b * 2816 + j];
    sr[tid] = s;
    __syncthreads();
    for (int st = 128; st >= 1; st >>= 1) {
        if (tid < st) sr[tid] += sr[tid + st];
        __syncthreads();
    }
    if (tid == 0) g_pgen[b] = 1.0f / (1.0f + expf(-(sr[0] + pb[0])));
}

__global__ void k_cat2048(const float* __restrict__ out_h, const float* __restrict__ cte_new,
                          int b0) {
    int idx = blockIdx.x * blockDim.x + threadIdx.x;
    if (idx >= NB * H4) return;
    int b = b0 + idx / H4, j = idx % H4;
    float v;
    if (j < 512) v = out_h[b * HH + j];
    else if (j < 1536) v = cte_new[b * D2H + (j - 512)];
    else v = g_ctd[b * HH + (j - 1536)];
    g_cat2048[b * H4 + j] = v;
}

__global__ void k_vocab(const float* __restrict__ extra, float* __restrict__ out_final, int b0) {
    int b = b0 + blockIdx.x;
    int tid = threadIdx.x;
    __shared__ float sr[1024];
    const float* lg = &g_logits[(size_t)b * VV];
    float mx = -1e30f;
    for (int v = tid; v < VV; v += 1024) mx = fmaxf(mx, lg[v]);
    sr[tid] = mx;
    __syncthreads();
    for (int s = 512; s >= 1; s >>= 1) {
        if (tid < s) sr[tid] = fmaxf(sr[tid], sr[tid + s]);
        __syncthreads();
    }
    mx = sr[0];
    __syncthreads();
    float sum = 0.f;
    for (int v = tid; v < VV; v += 1024) sum += __expf(lg[v] - mx);
    sr[tid] = sum;
    __syncthreads();
    for (int s = 512; s >= 1; s >>= 1) {
        if (tid < s) sr[tid] += sr[tid + s];
        __syncthreads();
    }
    float scale = g_pgen[b] / sr[0];
    float* fb = out_final + (size_t)b * (VV + OOV);
    for (int v = tid; v < VV; v += 1024) fb[v] = __expf(lg[v] - mx) * scale;
    for (int j = tid; j < OOV; j += 1024) fb[VV + j] = extra[b * OOV + j];
}

__global__ void k_scatter(const int* __restrict__ ebev, float* __restrict__ out_final, int b0) {
    int i = blockIdx.x * blockDim.x + threadIdx.x;
    if (i >= NB * NN) return;
    int idx = b0 * NN + i;
    int b = idx / NN;
    float w = (1.f - g_pgen[b]) * g_at[idx];
    atomicAdd(&out_final[(size_t)b * (VV + OOV) + ebev[idx]], w);
}

// ---------------- host ---------------------------------------------------
static void* sym(const void* s) {
    void* p = nullptr;
    cudaGetSymbolAddress(&p, s);
    return p;
}

extern "C" void kernel_launch(void* const* d_in, const int* in_sizes, int n_in,
                              void* d_out, int out_size) {
    const float* x_t   = (const float*)d_in[0];
    const float* dec_h = (const float*)d_in[1];
    const float* dec_c = (const float*)d_in[2];
    const float* enc_out = (const float*)d_in[3];
    const float* enc_mask = (const float*)d_in[4];
    const float* ct_e = (const float*)d_in[5];
    const float* extra_zeros = (const float*)d_in[6];
    const int*   ebev = (const int*)d_in[7];
    const float* sum_temporal = (const float*)d_in[8];
    const float* prev_s = (const float*)d_in[9];
    const float* x_input_w = (const float*)d_in[10];
    const float* x_input_b = (const float*)d_in[11];
    const float* lstm_w_ih = (const float*)d_in[12];
    const float* lstm_w_hh = (const float*)d_in[13];
    const float* lstm_b_ih = (const float*)d_in[14];
    const float* lstm_b_hh = (const float*)d_in[15];
    const float* pgen_w = (const float*)d_in[16];
    const float* pgen_b = (const float*)d_in[17];
    const float* V_w = (const float*)d_in[18];
    const float* V_b = (const float*)d_in[19];
    const float* V1_w = (const float*)d_in[20];
    const float* V1_b = (const float*)d_in[21];
    const float* Wh_w = (const float*)d_in[22];
    const float* Ws_w = (const float*)d_in[23];
    const float* Ws_b = (const float*)d_in[24];
    const float* v_w = (const float*)d_in[25];
    const float* Wprev_w = (const float*)d_in[26];
    const float* Wsd_w = (const float*)d_in[27];
    const float* Wsd_b = (const float*)d_in[28];
    const float* vd_w = (const float*)d_in[29];

    float* out = (float*)d_out;
    float* out_final = out;
    float* out_h = out_final + (size_t)BB * (VV + OOV);
    float* out_c = out_h + (size_t)BB * HH;
    float* out_cte = out_c + (size_t)BB * HH;
    float* out_sumnew = out_cte + (size_t)BB * D2H;
    float* out_prevs = out_sumnew + (size_t)BB * NN;

    float* p_cat1280 = (float*)sym(g_cat1280);
    float* p_x = (float*)sym(g_x);
    float* p_cat768 = (float*)sym(g_cat768);
    float* p_w768 = (float*)sym(g_w768);
    float* p_gates = (float*)sym(g_gates);
    float* p_sthat = (float*)sym(g_sthat);
    float* p_sdec = (float*)sym(g_sdec);
    float* p_hdec = (float*)sym(g_hdec);
    float* p_et = (float*)sym(g_et);
    float* p_etd = (float*)sym(g_etd);
    float* p_cat2048 = (float*)sym(g_cat2048);
    float* p_out2 = (float*)sym(g_out2);
    float* p_logits = (float*)sym(g_logits);
    float* p_etpart = (float*)sym(g_etpart);
    float* p_etpartd = (float*)sym(g_etpartd);
    const __half* p_ench = (const __half*)sym(g_ench);
    const __half* p_wh16 = (const __half*)sym(g_wh16);

    static cudaStream_t s1 = nullptr, s2 = nullptr;
    static cudaEvent_t evL, evD, evA0, evT0;
    if (!s1) {
        cudaStreamCreateWithFlags(&s1, cudaStreamNonBlocking);
        cudaStreamCreateWithFlags(&s2, cudaStreamNonBlocking);
        cudaEventCreateWithFlags(&evL, cudaEventDisableTiming);
        cudaEventCreateWithFlags(&evD, cudaEventDisableTiming);
        cudaEventCreateWithFlags(&evA0, cudaEventDisableTiming);
        cudaEventCreateWithFlags(&evT0, cudaEventDisableTiming);
        cudaFuncSetAttribute(attn16, cudaFuncAttributeMaxDynamicSharedMemorySize, 4 * STG_BYTES);
    }

    // ---------- stream 0: front chain ----------
    k_cvt<<<(ENC4 + WH4 + 255) / 256, 256>>>(enc_out, Wh_w);
    k_cat1280<<<(BB * 1280 + 255) / 256, 256>>>(x_t, ct_e);
    gemm_h<<<dim3(2, 2), 256>>>(p_cat1280, x_input_w, x_input_b, nullptr,
                                p_x, nullptr, BB, EE, 1280, 0, 1);
    k_cat768<<<(BB * 768 + 255) / 256, 256>>>(dec_h);
    k_w768<<<(H4 * 768 + 255) / 256, 256>>>(lstm_w_ih, lstm_w_hh);
    gemm_h<<<dim3(16, 2), 256>>>(p_cat768, p_w768, nullptr, nullptr,
                                 p_gates, nullptr, BB, H4, 768, 0, 1);
    k_lstm<<<(BB * HH + 255) / 256, 256>>>(dec_c, lstm_b_ih, lstm_b_hh, out_h, out_c, out_prevs);
    cudaEventRecord(evL, 0);

    // ---------- stream s1: intra-decoder attention branch (|| attn16) ----------
    cudaStreamWaitEvent(s1, evL, 0);
    k_copy_prevs<<<(BB * TT * HH + 255) / 256, 256, 0, s1>>>(prev_s, out_prevs);
    gemm_h<<<dim3(4, 2), 256, 0, s1>>>(out_h, Wsd_w, Wsd_b, nullptr,
                                       p_hdec, nullptr, BB, HH, HH, 0, 1);
    gemm_h<<<dim3(4, 98), 256, 0, s1>>>(prev_s, Wprev_w, p_hdec, vd_w,
                                        nullptr, p_etpartd, BB * TT, HH, HH, 1, TT);
    k_reduce_et<<<(BB * TT + 255) / 256, 256, 0, s1>>>(p_etpartd, p_etd, BB * TT, 0, BB * TT, 4);
    k_attn_dec<<<BB, 64, 0, s1>>>();
    k_ctd<<<dim3(BB, 2), 256, 0, s1>>>(prev_s);
    cudaEventRecord(evD, s1);

    // ---------- stream 0: Ws projection + big attention in 2 chunks ----------
    gemm_h<<<dim3(8, 2), 256>>>(p_sthat, Ws_w, Ws_b, nullptr,
                                p_sdec, nullptr, BB, D2H, D2H, 0, 1);
    attn16<<<dim3(8, 400), 256, 4 * STG_BYTES>>>(p_ench, p_wh16, p_sdec, v_w, p_etpart, 0);
    cudaEventRecord(evA0, 0);
    attn16<<<dim3(8, 400), 256, 4 * STG_BYTES>>>(p_ench, p_wh16, p_sdec, v_w, p_etpart,
                                                 NB * NN);

    // ---------- tail chunk 0 on s2 (overlaps attn16 chunk 1) ----------
    cudaStreamWaitEvent(s2, evA0, 0);
    cudaStreamWaitEvent(s2, evD, 0);
    {
        const int b0 = 0;
        k_reduce_et<<<(NB * NN + 255) / 256, 256, 0, s2>>>(p_etpart, p_et, BB * NN,
                                                           b0 * NN, NB * NN, 8);
        k_attn_enc<<<NB, 512, 0, s2>>>(enc_mask, sum_temporal, out_sumnew, b0);
        k_cte_h<<<dim3(NB, 4), 256, 0, s2>>>(out_cte, b0);
        k_cat2816<<<(NB * 2816 + 255) / 256, 256, 0, s2>>>(out_cte, b0);
        k_pgen<<<NB, 256, 0, s2>>>(pgen_w, pgen_b, b0);
        k_cat2048<<<(NB * H4 + 255) / 256, 256, 0, s2>>>(out_h, out_cte, b0);
        gemm_h<<<dim3(4, 1), 256, 0, s2>>>(p_cat2048 + (size_t)b0 * H4, V_w, V_b, nullptr,
                                           p_out2 + (size_t)b0 * HH, nullptr,
                                           NB, HH, H4, 0, 1);
        gemm_h<<<dim3(391, 1), 256, 0, s2>>>(p_out2 + (size_t)b0 * HH, V1_w, V1_b, nullptr,
                                             p_logits + (size_t)b0 * VV, nullptr,
                                             NB, VV, HH, 0, 1);
        k_vocab<<<NB, 1024, 0, s2>>>(extra_zeros, out_final, b0);
        k_scatter<<<(NB * NN + 255) / 256, 256, 0, s2>>>(ebev, out_final, b0);
    }
    cudaEventRecord(evT0, s2);

    // ---------- tail chunk 1 on stream 0 ----------
    cudaStreamWaitEvent(0, evD, 0);
    {
        const int b0 = NB;
        k_reduce_et<<<(NB * NN + 255) / 256, 256>>>(p_etpart, p_et, BB * NN,
                                                    b0 * NN, NB * NN, 8);
        k_attn_enc<<<NB, 512>>>(enc_mask, sum_temporal, out_sumnew, b0);
        k_cte_h<<<dim3(NB, 4), 256>>>(out_cte, b0);
        k_cat2816<<<(NB * 2816 + 255) / 256, 256>>>(out_cte, b0);
        k_pgen<<<NB, 256>>>(pgen_w, pgen_b, b0);
        k_cat2048<<<(NB * H4 + 255) / 256, 256>>>(out_h, out_cte, b0);
        gemm_h<<<dim3(4, 1), 256>>>(p_cat2048 + (size_t)b0 * H4, V_w, V_b, nullptr,
                                    p_out2 + (size_t)b0 * HH, nullptr, NB, HH, H4, 0, 1);
        gemm_h<<<dim3(391, 1), 256>>>(p_out2 + (size_t)b0 * HH, V1_w, V1_b, nullptr,
                                      p_logits + (size_t)b0 * VV, nullptr, NB, VV, HH, 0, 1);
        k_vocab<<<NB, 1024>>>(extra_zeros, out_final, b0);
        k_scatter<<<(NB * NN + 255) / 256, 256>>>(ebev, out_final, b0);
    }

    // join side streams back into origin
    cudaStreamWaitEvent(0, evT0, 0);
}